// round 9
// baseline (speedup 1.0000x reference)
#include <cuda_runtime.h>
#include <cuda_bf16.h>
#include <cstdint>
#include <math.h>

// EulerRosenbrockModel: B=512, D=256, HID=1024, H_STEP=0.01
// phi(A)v = v + 1.5 B v + 1.5 B^2 v,  B = (h/3) J  (||B|| ~ 0.015)
// mma.sync bf16 tensor-pipe GEMMs; forward pass in bf16 double-split,
// corrections plain bf16. Split-K reduction fused into the S-GEMM via a
// deterministic last-CTA-reduces semaphore (counters reset in-kernel).
// 7 launches total: split, L, S+red, L, S+red, L, S+red.

static constexpr int BATCH = 512;
static constexpr int DIM   = 256;
static constexpr int HID   = 1024;
static constexpr int BD    = BATCH * DIM;

__device__ float g_T   [BATCH * HID];
__device__ float g_V   [BD];
__device__ float g_part[4 * BD];
__device__ int   g_cnt [64];                 // per-tile semaphores (zero-init)
__device__ __nv_bfloat16 g_ys [BATCH * 2 * DIM];
__device__ __nv_bfloat16 g_W1s[HID   * 2 * DIM];
__device__ __nv_bfloat16 g_W2s[DIM   * 2 * HID];
__device__ __nv_bfloat16 g_Ts [BATCH * 2 * HID];
__device__ __nv_bfloat16 g_Pp [BATCH * HID];
__device__ __nv_bfloat16 g_Vp [BD];
__device__ __nv_bfloat16 g_Up [BD];

// ---------------- low-level helpers ----------------
__device__ __forceinline__ uint32_t smem_u32(const void* p) {
    uint32_t a;
    asm("{ .reg .u64 t; cvta.to.shared.u64 t, %1; cvt.u32.u64 %0, t; }"
        : "=r"(a) : "l"(p));
    return a;
}
__device__ __forceinline__ void cp16(uint32_t dst, const void* src) {
    asm volatile("cp.async.cg.shared.global [%0], [%1], 16;" :: "r"(dst), "l"(src));
}
__device__ __forceinline__ void cp_commit() {
    asm volatile("cp.async.commit_group;" ::: "memory");
}
template<int N>
__device__ __forceinline__ void cp_wait() {
    asm volatile("cp.async.wait_group %0;" :: "n"(N) : "memory");
}
__device__ __forceinline__ void ldm4(uint32_t* r, uint32_t addr) {
    asm volatile("ldmatrix.sync.aligned.m8n8.x4.shared.b16 {%0,%1,%2,%3}, [%4];"
        : "=r"(r[0]), "=r"(r[1]), "=r"(r[2]), "=r"(r[3]) : "r"(addr));
}
__device__ __forceinline__ void mma_bf16(float* d, const uint32_t* a, const uint32_t* b) {
    asm volatile("mma.sync.aligned.m16n8k16.row.col.f32.bf16.bf16.f32 "
        "{%0,%1,%2,%3}, {%4,%5,%6,%7}, {%8,%9}, {%0,%1,%2,%3};"
        : "+f"(d[0]), "+f"(d[1]), "+f"(d[2]), "+f"(d[3])
        : "r"(a[0]), "r"(a[1]), "r"(a[2]), "r"(a[3]), "r"(b[0]), "r"(b[1]));
}
__device__ __forceinline__ void st_split(__nv_bfloat16* Cs, int Kw, int m, int n,
                                         float v0, float v1) {
    __nv_bfloat162 h = __floats2bfloat162_rn(v0, v1);
    float l0 = v0 - __bfloat162float(h.x);
    float l1 = v1 - __bfloat162float(h.y);
    __nv_bfloat162 l = __floats2bfloat162_rn(l0, l1);
    *(__nv_bfloat162*)&Cs[(size_t)m * (2 * Kw) + n]      = h;
    *(__nv_bfloat162*)&Cs[(size_t)m * (2 * Kw) + Kw + n] = l;
}

#define MODE_TANH 0
#define MODE_MULS 1

// ---------------- L-shape GEMM (512 x HID) ----------------
// CTA tile 32x64, 8 warps, 4-stage cp.async ring, one sync per chunk.
// NREG=3: split precision (12 chunks over hi*hi/hi*lo/lo*hi); NREG=1: plain.
template<int MODE, int NREG>
__global__ void __launch_bounds__(256)
mmagemm(const __nv_bfloat16* __restrict__ A, int lda,
        const __nv_bfloat16* __restrict__ Bw, int ldb, int Ka,
        float* __restrict__ C, __nv_bfloat16* __restrict__ Cs,
        int Nglob, const float* __restrict__ bias, const float* __restrict__ tanhT)
{
    constexpr int CHUNKS = 4 * NREG;
    constexpr int STAGE  = 12288;
    __shared__ __align__(1024) char smem[4 * STAGE];
    const uint32_t sb = smem_u32(smem);

    const int tid = threadIdx.x;
    const int wid = tid >> 5;
    const int lid = tid & 31;
    const int wm  = wid >> 2;
    const int wn  = wid & 3;
    const int m0  = blockIdx.y * 32;
    const int n0  = blockIdx.x * 64;

    float acc[2][4];
    #pragma unroll
    for (int g = 0; g < 2; g++)
        #pragma unroll
        for (int q = 0; q < 4; q++) acc[g][q] = 0.0f;

    const int m_l = wm * 16 + ((lid >> 3) & 1) * 8 + (lid & 7);
    const int n_l = wn * 16 + (lid >> 4) * 8 + (lid & 7);
    const int a_so = (lid >> 4);
    const int b_so = ((lid >> 3) & 1);
    const uint32_t ax = (uint32_t)((m_l & 7) << 4);
    const uint32_t bx = (uint32_t)((n_l & 7) << 4);

    auto issue = [&](int cc, int st) {
        const int r  = (NREG == 3) ? (cc >> 2) : 0;
        const int kb = (cc & 3) * 64;
        const int ak = kb + (r == 2 ? Ka : 0);
        const int bk = kb + (r == 1 ? Ka : 0);
        const uint32_t ab = sb + st * STAGE;
        const uint32_t bb = ab + 4096;
        #pragma unroll
        for (int t = tid; t < 768; t += 256) {
            const int row = (t & 255) >> 3, seg = t & 7;
            const uint32_t sw = (uint32_t)(seg * 16) ^ (uint32_t)((row & 7) << 4);
            if (t < 256) {
                cp16(ab + row * 128 + sw,
                     A + (size_t)(m0 + row) * lda + ak + seg * 8);
            } else {
                const int rr = t >= 512 ? row + 32 : row;
                cp16(bb + rr * 128 + sw,
                     Bw + (size_t)(n0 + rr) * ldb + bk + seg * 8);
            }
        }
    };

    issue(0, 0); cp_commit();
    issue(1, 1); cp_commit();
    if (CHUNKS > 2) { issue(2, 2); cp_commit(); }

    #pragma unroll 1
    for (int c = 0; c < CHUNKS; c++) {
        const int rem = CHUNKS - 1 - c;
        if (rem >= 2)      cp_wait<2>();
        else if (rem == 1) cp_wait<1>();
        else               cp_wait<0>();
        __syncthreads();
        if (c + 3 < CHUNKS) { issue(c + 3, (c + 3) & 3); cp_commit(); }

        const uint32_t ab = sb + (c & 3) * STAGE;
        const uint32_t aRow = ab + m_l * 128;
        const uint32_t bRow = ab + 4096 + n_l * 128;
        #pragma unroll
        for (int k = 0; k < 4; k++) {
            uint32_t a0[4], b[4];
            const uint32_t as = (uint32_t)((k * 2 + a_so) * 16) ^ ax;
            const uint32_t bs = (uint32_t)((k * 2 + b_so) * 16) ^ bx;
            ldm4(a0, aRow + as);
            ldm4(b,  bRow + bs);
            mma_bf16(acc[0], a0, b);
            mma_bf16(acc[1], a0, b + 2);
        }
    }

    const int gid  = lid >> 2;
    const int tid4 = lid & 3;
    #pragma unroll
    for (int g = 0; g < 2; g++) {
        const int m = m0 + wm * 16 + gid;
        const int n = n0 + wn * 16 + g * 8 + tid4 * 2;
        const float* ac = acc[g];
        if (MODE == MODE_TANH) {
            const float b0v = bias[n], b1v = bias[n + 1];
            float v00 = tanhf(ac[0] + b0v), v01 = tanhf(ac[1] + b1v);
            float v10 = tanhf(ac[2] + b0v), v11 = tanhf(ac[3] + b1v);
            *(float2*)&C[(size_t)m * Nglob + n]       = make_float2(v00, v01);
            *(float2*)&C[(size_t)(m + 8) * Nglob + n] = make_float2(v10, v11);
            st_split(Cs, Nglob, m,     n, v00, v01);
            st_split(Cs, Nglob, m + 8, n, v10, v11);
        } else {
            float2 t0 = *(const float2*)&tanhT[(size_t)m * Nglob + n];
            float2 t1 = *(const float2*)&tanhT[(size_t)(m + 8) * Nglob + n];
            __nv_bfloat162 h0 = __floats2bfloat162_rn(
                ac[0] * (1.0f - t0.x * t0.x), ac[1] * (1.0f - t0.y * t0.y));
            __nv_bfloat162 h1 = __floats2bfloat162_rn(
                ac[2] * (1.0f - t1.x * t1.x), ac[3] * (1.0f - t1.y * t1.y));
            *(__nv_bfloat162*)&Cs[(size_t)m * Nglob + n]       = h0;
            *(__nv_bfloat162*)&Cs[(size_t)(m + 8) * Nglob + n] = h1;
        }
    }
}

// ---------------- S-shape GEMM (512 x 256) + fused split-K reduce ----------
// grid (4, 16, 4): z = K chunk. Each CTA writes its partial; the last CTA per
// tile (deterministic fixed-order sum) reduces and applies the epilogue.
// RMODE 0: fp32 out = sum + bias[n], bf16 outB = same
// RMODE 1: bf16 outB = aux + scale*sum
// RMODE 2: fp32 out = aux + scale*sum
template<int NREG, int RMODE>
__global__ void __launch_bounds__(256)
sgemm_red(const __nv_bfloat16* __restrict__ A, int lda,
          const __nv_bfloat16* __restrict__ Bw, int ldb, int Ka,
          const float* __restrict__ aux, float scale,
          float* __restrict__ outF, __nv_bfloat16* __restrict__ outB)
{
    constexpr int CHUNKS = 4 * NREG;
    constexpr int STAGE  = 12288;
    __shared__ __align__(1024) char smem[4 * STAGE];
    __shared__ int s_last;
    const uint32_t sb = smem_u32(smem);

    const int tid = threadIdx.x;
    const int wid = tid >> 5;
    const int lid = tid & 31;
    const int wm  = wid >> 2;
    const int wn  = wid & 3;
    const int m0  = blockIdx.y * 32;
    const int n0  = blockIdx.x * 64;
    const int zoff = blockIdx.z * 256;
    const int tile = blockIdx.y * 4 + blockIdx.x;

    float acc[2][4];
    #pragma unroll
    for (int g = 0; g < 2; g++)
        #pragma unroll
        for (int q = 0; q < 4; q++) acc[g][q] = 0.0f;

    const int m_l = wm * 16 + ((lid >> 3) & 1) * 8 + (lid & 7);
    const int n_l = wn * 16 + (lid >> 4) * 8 + (lid & 7);
    const int a_so = (lid >> 4);
    const int b_so = ((lid >> 3) & 1);
    const uint32_t ax = (uint32_t)((m_l & 7) << 4);
    const uint32_t bx = (uint32_t)((n_l & 7) << 4);

    auto issue = [&](int cc, int st) {
        const int r  = (NREG == 3) ? (cc >> 2) : 0;
        const int kb = (cc & 3) * 64;
        const int ak = zoff + kb + (r == 2 ? Ka : 0);
        const int bk = zoff + kb + (r == 1 ? Ka : 0);
        const uint32_t ab = sb + st * STAGE;
        const uint32_t bb = ab + 4096;
        #pragma unroll
        for (int t = tid; t < 768; t += 256) {
            const int row = (t & 255) >> 3, seg = t & 7;
            const uint32_t sw = (uint32_t)(seg * 16) ^ (uint32_t)((row & 7) << 4);
            if (t < 256) {
                cp16(ab + row * 128 + sw,
                     A + (size_t)(m0 + row) * lda + ak + seg * 8);
            } else {
                const int rr = t >= 512 ? row + 32 : row;
                cp16(bb + rr * 128 + sw,
                     Bw + (size_t)(n0 + rr) * ldb + bk + seg * 8);
            }
        }
    };

    issue(0, 0); cp_commit();
    issue(1, 1); cp_commit();
    if (CHUNKS > 2) { issue(2, 2); cp_commit(); }

    #pragma unroll 1
    for (int c = 0; c < CHUNKS; c++) {
        const int rem = CHUNKS - 1 - c;
        if (rem >= 2)      cp_wait<2>();
        else if (rem == 1) cp_wait<1>();
        else               cp_wait<0>();
        __syncthreads();
        if (c + 3 < CHUNKS) { issue(c + 3, (c + 3) & 3); cp_commit(); }

        const uint32_t ab = sb + (c & 3) * STAGE;
        const uint32_t aRow = ab + m_l * 128;
        const uint32_t bRow = ab + 4096 + n_l * 128;
        #pragma unroll
        for (int k = 0; k < 4; k++) {
            uint32_t a0[4], b[4];
            const uint32_t as = (uint32_t)((k * 2 + a_so) * 16) ^ ax;
            const uint32_t bs = (uint32_t)((k * 2 + b_so) * 16) ^ bx;
            ldm4(a0, aRow + as);
            ldm4(b,  bRow + bs);
            mma_bf16(acc[0], a0, b);
            mma_bf16(acc[1], a0, b + 2);
        }
    }

    // write partial for this z
    {
        float* Cb = g_part + (size_t)blockIdx.z * BD;
        const int gid  = lid >> 2;
        const int tid4 = lid & 3;
        #pragma unroll
        for (int g = 0; g < 2; g++) {
            const int m = m0 + wm * 16 + gid;
            const int n = n0 + wn * 16 + g * 8 + tid4 * 2;
            *(float2*)&Cb[(size_t)m * DIM + n]       = make_float2(acc[g][0], acc[g][1]);
            *(float2*)&Cb[(size_t)(m + 8) * DIM + n] = make_float2(acc[g][2], acc[g][3]);
        }
    }

    // semaphore: last CTA per tile reduces (fixed z order -> deterministic)
    __threadfence();
    __syncthreads();
    if (tid == 0) {
        int old = atomicAdd(&g_cnt[tile], 1);
        s_last = (old == 3);
    }
    __syncthreads();
    if (!s_last) return;
    __threadfence();

    #pragma unroll
    for (int it = 0; it < 2; it++) {
        const int t   = tid + it * 256;          // 0..511
        const int row = t >> 4, q = t & 15;
        const int m = m0 + row, n = n0 + q * 4;
        const size_t off = (size_t)m * DIM + n;
        float4 s0 = *(const float4*)&g_part[off];
        float4 s1 = *(const float4*)&g_part[BD + off];
        float4 s2 = *(const float4*)&g_part[2 * (size_t)BD + off];
        float4 s3 = *(const float4*)&g_part[3 * (size_t)BD + off];
        float4 r;
        r.x = (s0.x + s1.x) + (s2.x + s3.x);
        r.y = (s0.y + s1.y) + (s2.y + s3.y);
        r.z = (s0.z + s1.z) + (s2.z + s3.z);
        r.w = (s0.w + s1.w) + (s2.w + s3.w);
        if (RMODE == 0) {
            float4 b = *(const float4*)&aux[n];
            r.x += b.x; r.y += b.y; r.z += b.z; r.w += b.w;
            *(float4*)&outF[off] = r;
            __nv_bfloat162 h0 = __floats2bfloat162_rn(r.x, r.y);
            __nv_bfloat162 h1 = __floats2bfloat162_rn(r.z, r.w);
            *(__nv_bfloat162*)&outB[off]     = h0;
            *(__nv_bfloat162*)&outB[off + 2] = h1;
        } else {
            float4 b = *(const float4*)&aux[off];
            r.x = fmaf(scale, r.x, b.x); r.y = fmaf(scale, r.y, b.y);
            r.z = fmaf(scale, r.z, b.z); r.w = fmaf(scale, r.w, b.w);
            if (RMODE == 1) {
                __nv_bfloat162 h0 = __floats2bfloat162_rn(r.x, r.y);
                __nv_bfloat162 h1 = __floats2bfloat162_rn(r.z, r.w);
                *(__nv_bfloat162*)&outB[off]     = h0;
                *(__nv_bfloat162*)&outB[off + 2] = h1;
            } else {
                *(float4*)&outF[off] = r;
            }
        }
    }
    if (tid == 0) g_cnt[tile] = 0;   // reset for the next launch / replay
}

// fused split of y, W1, W2 -> split bf16 panels (one launch)
__global__ void __launch_bounds__(256)
split_all(const float* __restrict__ y, const float* __restrict__ W1,
          const float* __restrict__ W2,
          __nv_bfloat16* __restrict__ ys, __nv_bfloat16* __restrict__ W1s,
          __nv_bfloat16* __restrict__ W2s)
{
    int b = blockIdx.x;
    const float* in;
    __nv_bfloat16* outs;
    int K;
    if (b < 128)      { in = y;  outs = ys;  K = DIM; }
    else if (b < 384) { in = W1; outs = W1s; K = DIM;  b -= 128; }
    else              { in = W2; outs = W2s; K = HID;  b -= 384; }

    const int e4 = (b * 256 + threadIdx.x) * 4;
    const int row = e4 / K, k = e4 % K;
    float4 v = *(const float4*)&in[e4];
    __nv_bfloat162 h0 = __floats2bfloat162_rn(v.x, v.y);
    __nv_bfloat162 h1 = __floats2bfloat162_rn(v.z, v.w);
    __nv_bfloat162 l0 = __floats2bfloat162_rn(v.x - __bfloat162float(h0.x),
                                              v.y - __bfloat162float(h0.y));
    __nv_bfloat162 l1 = __floats2bfloat162_rn(v.z - __bfloat162float(h1.x),
                                              v.w - __bfloat162float(h1.y));
    *(__nv_bfloat162*)&outs[(size_t)row * 2 * K + k]         = h0;
    *(__nv_bfloat162*)&outs[(size_t)row * 2 * K + k + 2]     = h1;
    *(__nv_bfloat162*)&outs[(size_t)row * 2 * K + K + k]     = l0;
    *(__nv_bfloat162*)&outs[(size_t)row * 2 * K + K + k + 2] = l1;
}

extern "C" void kernel_launch(void* const* d_in, const int* in_sizes, int n_in,
                              void* d_out, int out_size)
{
    const float* y  = (const float*)d_in[0];
    const float* W1 = (const float*)d_in[1];
    const float* b1 = (const float*)d_in[2];
    const float* W2 = (const float*)d_in[3];
    const float* b2 = (const float*)d_in[4];
    float* out = (float*)d_out;

    float *pT, *pV;
    __nv_bfloat16 *pYs, *pW1s, *pW2s, *pTs, *pPp, *pVp, *pUp;
    cudaGetSymbolAddress((void**)&pT,   g_T);
    cudaGetSymbolAddress((void**)&pV,   g_V);
    cudaGetSymbolAddress((void**)&pYs,  g_ys);
    cudaGetSymbolAddress((void**)&pW1s, g_W1s);
    cudaGetSymbolAddress((void**)&pW2s, g_W2s);
    cudaGetSymbolAddress((void**)&pTs,  g_Ts);
    cudaGetSymbolAddress((void**)&pPp,  g_Pp);
    cudaGetSymbolAddress((void**)&pVp,  g_Vp);
    cudaGetSymbolAddress((void**)&pUp,  g_Up);

    dim3 gL(HID / 64, BATCH / 32, 1);   // (16,16,1) = 256 CTAs
    dim3 gS(DIM / 64, BATCH / 32, 4);   // ( 4,16,4) = 256 CTAs, 64 tiles

    const float c3 = 0.01f / 3.0f;

    split_all<<<640, 256>>>(y, W1, W2, pYs, pW1s, pW2s);

    // forward (split precision): T = tanh(y W1^T + b1);  V = T W2^T + b2
    mmagemm<MODE_TANH, 3><<<gL, 256>>>(pYs, 2 * DIM, pW1s, 2 * DIM, DIM,
                                       pT, pTs, HID, b1, nullptr);
    sgemm_red<3, 0><<<gS, 256>>>(pTs, 2 * HID, pW2s, 2 * HID, HID,
                                 b2, 0.0f, pV, pVp);

    // u = v + B v   (plain bf16 corrections)
    mmagemm<MODE_MULS, 1><<<gL, 256>>>(pVp, DIM, pW1s, 2 * DIM, 0,
                                       nullptr, pPp, HID, nullptr, pT);
    sgemm_red<1, 1><<<gS, 256>>>(pPp, HID, pW2s, 2 * HID, 0,
                                 pV, c3, nullptr, pUp);

    // out = v + 1.5 B u
    mmagemm<MODE_MULS, 1><<<gL, 256>>>(pUp, DIM, pW1s, 2 * DIM, 0,
                                       nullptr, pPp, HID, nullptr, pT);
    sgemm_red<1, 2><<<gS, 256>>>(pPp, HID, pW2s, 2 * HID, 0,
                                 pV, 1.5f * c3, out, nullptr);
}

// round 10
// speedup vs baseline: 1.3381x; 1.3381x over previous
#include <cuda_runtime.h>
#include <cuda_bf16.h>
#include <cstdint>
#include <math.h>

// EulerRosenbrockModel: B=512, D=256, HID=1024, H_STEP=0.01
// phi(A)v = (I-B)^{-1}(I+B/2)v ~ v + 1.5 B v   (B = (h/3)J, ||Bv||/||v|| ~ 2e-3,
//   dropped 1.5 B^2 v term ~ 8e-6 relative; bf16 path error ~1.3e-5)
// Chain: split -> L1(split bf16) -> S1(split) -> reduce(v) -> L2(plain) ->
//        S2(plain) -> reduce(out).  7 launches.

static constexpr int BATCH = 512;
static constexpr int DIM   = 256;
static constexpr int HID   = 1024;
static constexpr int BD    = BATCH * DIM;

__device__ float g_T   [BATCH * HID];
__device__ float g_V   [BD];
__device__ float g_part[4 * BD];
__device__ __nv_bfloat16 g_ys [BATCH * 2 * DIM];
__device__ __nv_bfloat16 g_W1s[HID   * 2 * DIM];
__device__ __nv_bfloat16 g_W2s[DIM   * 2 * HID];
__device__ __nv_bfloat16 g_Ts [BATCH * 2 * HID];
__device__ __nv_bfloat16 g_Pp [BATCH * HID];
__device__ __nv_bfloat16 g_Vp [BD];

// ---------------- low-level helpers ----------------
__device__ __forceinline__ uint32_t smem_u32(const void* p) {
    uint32_t a;
    asm("{ .reg .u64 t; cvta.to.shared.u64 t, %1; cvt.u32.u64 %0, t; }"
        : "=r"(a) : "l"(p));
    return a;
}
__device__ __forceinline__ void cp16(uint32_t dst, const void* src) {
    asm volatile("cp.async.cg.shared.global [%0], [%1], 16;" :: "r"(dst), "l"(src));
}
__device__ __forceinline__ void cp_commit() {
    asm volatile("cp.async.commit_group;" ::: "memory");
}
template<int N>
__device__ __forceinline__ void cp_wait() {
    asm volatile("cp.async.wait_group %0;" :: "n"(N) : "memory");
}
__device__ __forceinline__ void ldm4(uint32_t* r, uint32_t addr) {
    asm volatile("ldmatrix.sync.aligned.m8n8.x4.shared.b16 {%0,%1,%2,%3}, [%4];"
        : "=r"(r[0]), "=r"(r[1]), "=r"(r[2]), "=r"(r[3]) : "r"(addr));
}
__device__ __forceinline__ void mma_bf16(float* d, const uint32_t* a, const uint32_t* b) {
    asm volatile("mma.sync.aligned.m16n8k16.row.col.f32.bf16.bf16.f32 "
        "{%0,%1,%2,%3}, {%4,%5,%6,%7}, {%8,%9}, {%0,%1,%2,%3};"
        : "+f"(d[0]), "+f"(d[1]), "+f"(d[2]), "+f"(d[3])
        : "r"(a[0]), "r"(a[1]), "r"(a[2]), "r"(a[3]), "r"(b[0]), "r"(b[1]));
}
__device__ __forceinline__ void st_split(__nv_bfloat16* Cs, int Kw, int m, int n,
                                         float v0, float v1) {
    __nv_bfloat162 h = __floats2bfloat162_rn(v0, v1);
    float l0 = v0 - __bfloat162float(h.x);
    float l1 = v1 - __bfloat162float(h.y);
    __nv_bfloat162 l = __floats2bfloat162_rn(l0, l1);
    *(__nv_bfloat162*)&Cs[(size_t)m * (2 * Kw) + n]      = h;
    *(__nv_bfloat162*)&Cs[(size_t)m * (2 * Kw) + Kw + n] = l;
}

#define MODE_TANH 0
#define MODE_MULS 1
#define MODE_PART 2

// CTA tile 32x64, 8 warps, 4-stage cp.async ring, one sync per chunk.
// NREG=3: split precision (12 chunks); NREG=1: plain bf16 (4 chunks).
template<int MODE, int NREG>
__global__ void __launch_bounds__(256)
mmagemm(const __nv_bfloat16* __restrict__ A, int lda,
        const __nv_bfloat16* __restrict__ Bw, int ldb, int Ka,
        float* __restrict__ C, __nv_bfloat16* __restrict__ Cs,
        int Nglob, const float* __restrict__ bias, const float* __restrict__ tanhT)
{
    constexpr int CHUNKS = 4 * NREG;
    constexpr int STAGE  = 12288;           // 4KB A + 8KB B
    __shared__ __align__(1024) char smem[4 * STAGE];
    const uint32_t sb = smem_u32(smem);

    const int tid = threadIdx.x;
    const int wid = tid >> 5;
    const int lid = tid & 31;
    const int wm  = wid >> 2;
    const int wn  = wid & 3;
    const int m0  = blockIdx.y * 32;
    const int n0  = blockIdx.x * 64;
    const int zoff = blockIdx.z * 256;

    float acc[2][4];
    #pragma unroll
    for (int g = 0; g < 2; g++)
        #pragma unroll
        for (int q = 0; q < 4; q++) acc[g][q] = 0.0f;

    const int m_l = wm * 16 + ((lid >> 3) & 1) * 8 + (lid & 7);
    const int n_l = wn * 16 + (lid >> 4) * 8 + (lid & 7);
    const int a_so = (lid >> 4);
    const int b_so = ((lid >> 3) & 1);
    const uint32_t ax = (uint32_t)((m_l & 7) << 4);
    const uint32_t bx = (uint32_t)((n_l & 7) << 4);

    auto issue = [&](int cc, int st) {
        const int r  = (NREG == 3) ? (cc >> 2) : 0;
        const int kb = (cc & 3) * 64;
        const int ak = zoff + kb + (r == 2 ? Ka : 0);
        const int bk = zoff + kb + (r == 1 ? Ka : 0);
        const uint32_t ab = sb + st * STAGE;
        const uint32_t bb = ab + 4096;
        #pragma unroll
        for (int t = tid; t < 768; t += 256) {
            const int row = (t & 255) >> 3, seg = t & 7;
            const uint32_t sw = (uint32_t)(seg * 16) ^ (uint32_t)((row & 7) << 4);
            if (t < 256) {
                cp16(ab + row * 128 + sw,
                     A + (size_t)(m0 + row) * lda + ak + seg * 8);
            } else {
                const int rr = t >= 512 ? row + 32 : row;
                cp16(bb + rr * 128 + sw,
                     Bw + (size_t)(n0 + rr) * ldb + bk + seg * 8);
            }
        }
    };

    issue(0, 0); cp_commit();
    issue(1, 1); cp_commit();
    if (CHUNKS > 2) { issue(2, 2); cp_commit(); }

    #pragma unroll 1
    for (int c = 0; c < CHUNKS; c++) {
        const int rem = CHUNKS - 1 - c;
        if (rem >= 2)      cp_wait<2>();
        else if (rem == 1) cp_wait<1>();
        else               cp_wait<0>();
        __syncthreads();
        if (c + 3 < CHUNKS) { issue(c + 3, (c + 3) & 3); cp_commit(); }

        const uint32_t ab = sb + (c & 3) * STAGE;
        const uint32_t aRow = ab + m_l * 128;
        const uint32_t bRow = ab + 4096 + n_l * 128;
        #pragma unroll
        for (int k = 0; k < 4; k++) {
            uint32_t a0[4], b[4];
            const uint32_t as = (uint32_t)((k * 2 + a_so) * 16) ^ ax;
            const uint32_t bs = (uint32_t)((k * 2 + b_so) * 16) ^ bx;
            ldm4(a0, aRow + as);
            ldm4(b,  bRow + bs);
            mma_bf16(acc[0], a0, b);
            mma_bf16(acc[1], a0, b + 2);
        }
    }

    const int gid  = lid >> 2;
    const int tid4 = lid & 3;
    #pragma unroll
    for (int g = 0; g < 2; g++) {
        const int m = m0 + wm * 16 + gid;
        const int n = n0 + wn * 16 + g * 8 + tid4 * 2;
        const float* ac = acc[g];
        if (MODE == MODE_TANH) {
            const float b0v = bias[n], b1v = bias[n + 1];
            float v00 = tanhf(ac[0] + b0v), v01 = tanhf(ac[1] + b1v);
            float v10 = tanhf(ac[2] + b0v), v11 = tanhf(ac[3] + b1v);
            *(float2*)&C[(size_t)m * Nglob + n]       = make_float2(v00, v01);
            *(float2*)&C[(size_t)(m + 8) * Nglob + n] = make_float2(v10, v11);
            st_split(Cs, Nglob, m,     n, v00, v01);
            st_split(Cs, Nglob, m + 8, n, v10, v11);
        } else if (MODE == MODE_MULS) {
            float2 t0 = *(const float2*)&tanhT[(size_t)m * Nglob + n];
            float2 t1 = *(const float2*)&tanhT[(size_t)(m + 8) * Nglob + n];
            __nv_bfloat162 h0 = __floats2bfloat162_rn(
                ac[0] * (1.0f - t0.x * t0.x), ac[1] * (1.0f - t0.y * t0.y));
            __nv_bfloat162 h1 = __floats2bfloat162_rn(
                ac[2] * (1.0f - t1.x * t1.x), ac[3] * (1.0f - t1.y * t1.y));
            *(__nv_bfloat162*)&Cs[(size_t)m * Nglob + n]       = h0;
            *(__nv_bfloat162*)&Cs[(size_t)(m + 8) * Nglob + n] = h1;
        } else {
            float* Cb = C + (size_t)blockIdx.z * BD;
            *(float2*)&Cb[(size_t)m * Nglob + n]       = make_float2(ac[0], ac[1]);
            *(float2*)&Cb[(size_t)(m + 8) * Nglob + n] = make_float2(ac[2], ac[3]);
        }
    }
}

// fused split of y, W1, W2 -> split bf16 panels (one launch)
__global__ void __launch_bounds__(256)
split_all(const float* __restrict__ y, const float* __restrict__ W1,
          const float* __restrict__ W2,
          __nv_bfloat16* __restrict__ ys, __nv_bfloat16* __restrict__ W1s,
          __nv_bfloat16* __restrict__ W2s)
{
    int b = blockIdx.x;
    const float* in;
    __nv_bfloat16* outs;
    int K;
    if (b < 128)      { in = y;  outs = ys;  K = DIM; }
    else if (b < 384) { in = W1; outs = W1s; K = DIM;  b -= 128; }
    else              { in = W2; outs = W2s; K = HID;  b -= 384; }

    const int e4 = (b * 256 + threadIdx.x) * 4;
    const int row = e4 / K, k = e4 % K;
    float4 v = *(const float4*)&in[e4];
    __nv_bfloat162 h0 = __floats2bfloat162_rn(v.x, v.y);
    __nv_bfloat162 h1 = __floats2bfloat162_rn(v.z, v.w);
    __nv_bfloat162 l0 = __floats2bfloat162_rn(v.x - __bfloat162float(h0.x),
                                              v.y - __bfloat162float(h0.y));
    __nv_bfloat162 l1 = __floats2bfloat162_rn(v.z - __bfloat162float(h1.x),
                                              v.w - __bfloat162float(h1.y));
    *(__nv_bfloat162*)&outs[(size_t)row * 2 * K + k]         = h0;
    *(__nv_bfloat162*)&outs[(size_t)row * 2 * K + k + 2]     = h1;
    *(__nv_bfloat162*)&outs[(size_t)row * 2 * K + K + k]     = l0;
    *(__nv_bfloat162*)&outs[(size_t)row * 2 * K + K + k + 2] = l1;
}

// RMODE 0: fp32 out = sum + bias, plain bf16 outs
// RMODE 2: fp32 out = aux + scale*sum
template<int RMODE>
__global__ void __launch_bounds__(256)
reduce_ep(const float* __restrict__ part, const float* __restrict__ aux,
          float scale, float* __restrict__ out, __nv_bfloat16* __restrict__ outs)
{
    const int e4 = (blockIdx.x * 256 + threadIdx.x) * 4;
    float4 s0 = *(const float4*)&part[e4];
    float4 s1 = *(const float4*)&part[BD     + e4];
    float4 s2 = *(const float4*)&part[BD * 2 + e4];
    float4 s3 = *(const float4*)&part[BD * 3 + e4];
    float4 r;
    r.x = (s0.x + s1.x) + (s2.x + s3.x);
    r.y = (s0.y + s1.y) + (s2.y + s3.y);
    r.z = (s0.z + s1.z) + (s2.z + s3.z);
    r.w = (s0.w + s1.w) + (s2.w + s3.w);
    if (RMODE == 0) {
        float4 b = *(const float4*)&aux[e4 & (DIM - 1)];
        r.x += b.x; r.y += b.y; r.z += b.z; r.w += b.w;
        *(float4*)&out[e4] = r;
        __nv_bfloat162 h0 = __floats2bfloat162_rn(r.x, r.y);
        __nv_bfloat162 h1 = __floats2bfloat162_rn(r.z, r.w);
        *(__nv_bfloat162*)&outs[e4]     = h0;
        *(__nv_bfloat162*)&outs[e4 + 2] = h1;
    } else {
        float4 b = *(const float4*)&aux[e4];
        r.x = fmaf(scale, r.x, b.x); r.y = fmaf(scale, r.y, b.y);
        r.z = fmaf(scale, r.z, b.z); r.w = fmaf(scale, r.w, b.w);
        *(float4*)&out[e4] = r;
    }
}

extern "C" void kernel_launch(void* const* d_in, const int* in_sizes, int n_in,
                              void* d_out, int out_size)
{
    const float* y  = (const float*)d_in[0];
    const float* W1 = (const float*)d_in[1];
    const float* b1 = (const float*)d_in[2];
    const float* W2 = (const float*)d_in[3];
    const float* b2 = (const float*)d_in[4];
    float* out = (float*)d_out;

    float *pT, *pV, *pPart;
    __nv_bfloat16 *pYs, *pW1s, *pW2s, *pTs, *pPp, *pVp;
    cudaGetSymbolAddress((void**)&pT,    g_T);
    cudaGetSymbolAddress((void**)&pV,    g_V);
    cudaGetSymbolAddress((void**)&pPart, g_part);
    cudaGetSymbolAddress((void**)&pYs,   g_ys);
    cudaGetSymbolAddress((void**)&pW1s,  g_W1s);
    cudaGetSymbolAddress((void**)&pW2s,  g_W2s);
    cudaGetSymbolAddress((void**)&pTs,   g_Ts);
    cudaGetSymbolAddress((void**)&pPp,   g_Pp);
    cudaGetSymbolAddress((void**)&pVp,   g_Vp);

    dim3 gL(HID / 64, BATCH / 32, 1);   // (16,16,1) = 256 CTAs
    dim3 gS(DIM / 64, BATCH / 32, 4);   // ( 4,16,4) = 256 CTAs
    const int gR = BD / (256 * 4);      // 128

    const float c3 = 0.01f / 3.0f;

    split_all<<<640, 256>>>(y, W1, W2, pYs, pW1s, pW2s);

    // forward (split precision): T = tanh(y W1^T + b1);  V = T W2^T + b2
    mmagemm<MODE_TANH, 3><<<gL, 256>>>(pYs, 2 * DIM, pW1s, 2 * DIM, DIM,
                                       pT, pTs, HID, b1, nullptr);
    mmagemm<MODE_PART, 3><<<gS, 256>>>(pTs, 2 * HID, pW2s, 2 * HID, HID,
                                       pPart, nullptr, DIM, nullptr, nullptr);
    reduce_ep<0><<<gR, 256>>>(pPart, b2, 0.0f, pV, pVp);

    // out = v + 1.5 B v   (single correction, plain bf16)
    mmagemm<MODE_MULS, 1><<<gL, 256>>>(pVp, DIM, pW1s, 2 * DIM, 0,
                                       nullptr, pPp, HID, nullptr, pT);
    mmagemm<MODE_PART, 1><<<gS, 256>>>(pPp, HID, pW2s, 2 * HID, 0,
                                       pPart, nullptr, DIM, nullptr, nullptr);
    reduce_ep<2><<<gR, 256>>>(pPart, pV, 1.5f * c3, out, nullptr);
}